// round 7
// baseline (speedup 1.0000x reference)
#include <cuda_runtime.h>
#include <math.h>

#define CCH   64
#define NPIX  (512*512)
#define TP    256          // stats tile pixels
#define GX    148          // stats grid.x
#define NT    (NPIX/TP)    // 1024 tiles
#define SP    68           // stats sorted-tile pitch (floats)
#define PITCH 68           // 64x64 matrix smem pitch (floats)
#define TPA   512          // apply tile pixels
#define APA   544          // apply smem pitch (floats); 544 = 17*32
#define NS_ITERS 7

// ---------------- global scratch (static __device__, no allocations) ----------------
__device__ float g_gram[2*2*GX*4*4096];  // [side][gy][block][ll][64*64]
__device__ float g_s1p [2*2*GX*4*64];    // per-slab channel sums
__device__ float g_cntp[2*2*GX*4];       // per-slab counts
__device__ float g_S1c[8*64];
__device__ float g_S1s[8*64];
__device__ float g_cntc[8];
__device__ float g_cnts[8];
__device__ float g_S2c[8*4096];
__device__ float g_S2s[8*4096];
__device__ float g_Tt[8*4096];   // T transposed: g_Tt[l][k*64+c] = T[c][k]
__device__ float g_bv[8*64];     // b = mu_s - T mu_c (0 if invalid)

#define FMA16(ACC, AV, BV) do { \
    ACC[0]  += AV.x*BV.x; ACC[1]  += AV.x*BV.y; ACC[2]  += AV.x*BV.z; ACC[3]  += AV.x*BV.w; \
    ACC[4]  += AV.y*BV.x; ACC[5]  += AV.y*BV.y; ACC[6]  += AV.y*BV.z; ACC[7]  += AV.y*BV.w; \
    ACC[8]  += AV.z*BV.x; ACC[9]  += AV.z*BV.y; ACC[10] += AV.z*BV.z; ACC[11] += AV.z*BV.w; \
    ACC[12] += AV.w*BV.x; ACC[13] += AV.w*BV.y; ACC[14] += AV.w*BV.z; ACC[15] += AV.w*BV.w; \
} while (0)

// ---------------- stats: sorted-compact staging, contiguous Gram loop ----------------
// grid (GX, 2, 2): y = label-group (4 labels), z = side. 256 threads.
__global__ void __launch_bounds__(256, 2)
stats_kernel(const float* __restrict__ Xc, const float* __restrict__ Xs,
             const int* __restrict__ segc, const int* __restrict__ segs)
{
    extern __shared__ float As[];            // 256 * SP floats, label-sorted rows
    __shared__ int sh_hist[4], sh_off[4], sh_seg[5];

    const int tid  = threadIdx.x;
    const int gy   = blockIdx.y;
    const int side = blockIdx.z;
    const float* X    = side ? Xs : Xc;
    const int*   segp = side ? segs : segc;
    const int l0 = gy * 4;
    const int ti = tid >> 4, tj = tid & 15;
    float* Ap = As + 4*ti;
    float* Bp = As + 4*tj;

    float acc[4][16];
#pragma unroll
    for (int a = 0; a < 4; a++)
#pragma unroll
        for (int b = 0; b < 16; b++) acc[a][b] = 0.f;
    float s1[4] = {0.f,0.f,0.f,0.f};
    float cl[4] = {0.f,0.f,0.f,0.f};
    const int sc = tid & 63, sq = tid >> 6;

    for (int tile = blockIdx.x; tile < NT; tile += GX) {
        const int base = tile * TP;
        __syncthreads();                       // guard As reuse
        if (tid < 4) sh_hist[tid] = 0;
        __syncthreads();
        int lb = segp[base + tid];
        lb = lb < 0 ? 0 : (lb > 7 ? 7 : lb);
        const int lidx = lb - l0;
        const bool ing = (lidx >= 0) && (lidx < 4);
        if (ing) atomicAdd(&sh_hist[lidx], 1);
        __syncthreads();
        if (tid == 0) {
            int a = 0;
#pragma unroll
            for (int i = 0; i < 4; i++) { sh_seg[i] = a; sh_off[i] = a; a += sh_hist[i]; }
            sh_seg[4] = a;
        }
        __syncthreads();
        const int sp = ing ? atomicAdd(&sh_off[lidx], 1) : -1;
        // stage own pixel's 64 channels into sorted row sp (coalesced LDG per c)
        if (sp >= 0) {
            float* dst = As + sp*SP;
            const float* src = X + base + tid;
#pragma unroll 8
            for (int c = 0; c < 64; c++) dst[c] = src[(size_t)c*NPIX];
        }
        __syncthreads();

#pragma unroll
        for (int ll = 0; ll < 4; ll++) {
            const int s = sh_seg[ll], e = sh_seg[ll+1];
            int k = s;
#define GB(LL, KK) { const float4 av = *(const float4*)&Ap[(KK)*SP]; \
                     const float4 bv = *(const float4*)&Bp[(KK)*SP]; \
                     FMA16(acc[LL], av, bv); }
            for (; k + 4 <= e; k += 4) { GB(ll, k) GB(ll, k+1) GB(ll, k+2) GB(ll, k+3) }
            for (; k < e; k++) GB(ll, k)
        }
        // per-label channel sums: lanes read consecutive channels, conflict-free
#pragma unroll
        for (int ll = 0; ll < 4; ll++) {
            for (int k = sh_seg[ll] + sq; k < sh_seg[ll+1]; k += 4)
                s1[ll] += As[k*SP + sc];
        }
        if (tid == 0) {
#pragma unroll
            for (int ll = 0; ll < 4; ll++) cl[ll] += (float)(sh_seg[ll+1] - sh_seg[ll]);
        }
    }

    // flush partial Grams / s1 / cnt (non-atomic, own slab)
    const size_t sb = (size_t)(side*2 + gy)*GX + blockIdx.x;
    float* gp = g_gram + sb*16384;
#pragma unroll
    for (int ll = 0; ll < 4; ll++)
#pragma unroll
        for (int a = 0; a < 4; a++) {
            float4 v = make_float4(acc[ll][a*4+0], acc[ll][a*4+1],
                                   acc[ll][a*4+2], acc[ll][a*4+3]);
            *(float4*)&gp[ll*4096 + (4*ti + a)*64 + 4*tj] = v;
        }
#pragma unroll
    for (int ll = 0; ll < 4; ll++) {
        __syncthreads();
        As[tid] = s1[ll];
        __syncthreads();
        if (tid < 64)
            g_s1p[sb*256 + ll*64 + tid] = As[tid] + As[tid+64] + As[tid+128] + As[tid+192];
    }
    if (tid == 0) {
#pragma unroll
        for (int ll = 0; ll < 4; ll++) g_cntp[sb*4 + ll] = cl[ll];
    }
}

// ---------------- reduce partial Grams + s1 + cnt ----------------
__global__ void reduce_kernel() {
    const int idx = blockIdx.x * blockDim.x + threadIdx.x;
    if (idx < 65536) {
        const int side = idx >> 15, r = idx & 32767;
        const int l = r >> 12, gy = l >> 2, ll = l & 3;
        const float* p = g_gram + ((size_t)(side*2 + gy)*GX)*16384 + ll*4096 + (r & 4095);
        float s = 0.f;
#pragma unroll 4
        for (int b = 0; b < GX; b++) s += p[(size_t)b*16384];
        (side ? g_S2s : g_S2c)[r] = s;
    } else if (idx < 66560) {
        const int j = idx - 65536;
        const int side = j >> 9, r = j & 511;
        const int l = r >> 6, gy = l >> 2, ll = l & 3;
        const float* p = g_s1p + ((size_t)(side*2 + gy)*GX)*256 + ll*64 + (r & 63);
        float s = 0.f;
        for (int b = 0; b < GX; b++) s += p[(size_t)b*256];
        (side ? g_S1s : g_S1c)[r] = s;
    } else if (idx < 66576) {
        const int j = idx - 66560;
        const int side = j >> 3, l = j & 7, gy = l >> 2, ll = l & 3;
        const float* p = g_cntp + ((size_t)(side*2 + gy)*GX)*4 + ll;
        float s = 0.f;
        for (int b = 0; b < GX; b++) s += p[(size_t)b*4];
        (side ? g_cnts : g_cntc)[l] = s;
    }
}

// ---------------- 64x64 matmul helper (smem, pitch PITCH), float4 loads ----------------
__device__ __forceinline__ void mm64v(const float* __restrict__ A,
                                      const float* __restrict__ B,
                                      float (&acc)[16], int ti, int tj)
{
#pragma unroll 4
    for (int k0 = 0; k0 < 64; k0 += 4) {
        const float4 a0 = *(const float4*)&A[(4*ti+0)*PITCH + k0];
        const float4 a1 = *(const float4*)&A[(4*ti+1)*PITCH + k0];
        const float4 a2 = *(const float4*)&A[(4*ti+2)*PITCH + k0];
        const float4 a3 = *(const float4*)&A[(4*ti+3)*PITCH + k0];
        const float4 b0 = *(const float4*)&B[(k0+0)*PITCH + 4*tj];
        const float4 b1 = *(const float4*)&B[(k0+1)*PITCH + 4*tj];
        const float4 b2 = *(const float4*)&B[(k0+2)*PITCH + 4*tj];
        const float4 b3 = *(const float4*)&B[(k0+3)*PITCH + 4*tj];
        acc[0]+=a0.x*b0.x; acc[1]+=a0.x*b0.y; acc[2]+=a0.x*b0.z; acc[3]+=a0.x*b0.w;
        acc[4]+=a1.x*b0.x; acc[5]+=a1.x*b0.y; acc[6]+=a1.x*b0.z; acc[7]+=a1.x*b0.w;
        acc[8]+=a2.x*b0.x; acc[9]+=a2.x*b0.y; acc[10]+=a2.x*b0.z; acc[11]+=a2.x*b0.w;
        acc[12]+=a3.x*b0.x; acc[13]+=a3.x*b0.y; acc[14]+=a3.x*b0.z; acc[15]+=a3.x*b0.w;
        acc[0]+=a0.y*b1.x; acc[1]+=a0.y*b1.y; acc[2]+=a0.y*b1.z; acc[3]+=a0.y*b1.w;
        acc[4]+=a1.y*b1.x; acc[5]+=a1.y*b1.y; acc[6]+=a1.y*b1.z; acc[7]+=a1.y*b1.w;
        acc[8]+=a2.y*b1.x; acc[9]+=a2.y*b1.y; acc[10]+=a2.y*b1.z; acc[11]+=a2.y*b1.w;
        acc[12]+=a3.y*b1.x; acc[13]+=a3.y*b1.y; acc[14]+=a3.y*b1.z; acc[15]+=a3.y*b1.w;
        acc[0]+=a0.z*b2.x; acc[1]+=a0.z*b2.y; acc[2]+=a0.z*b2.z; acc[3]+=a0.z*b2.w;
        acc[4]+=a1.z*b2.x; acc[5]+=a1.z*b2.y; acc[6]+=a1.z*b2.z; acc[7]+=a1.z*b2.w;
        acc[8]+=a2.z*b2.x; acc[9]+=a2.z*b2.y; acc[10]+=a2.z*b2.z; acc[11]+=a2.z*b2.w;
        acc[12]+=a3.z*b2.x; acc[13]+=a3.z*b2.y; acc[14]+=a3.z*b2.z; acc[15]+=a3.z*b2.w;
        acc[0]+=a0.w*b3.x; acc[1]+=a0.w*b3.y; acc[2]+=a0.w*b3.z; acc[3]+=a0.w*b3.w;
        acc[4]+=a1.w*b3.x; acc[5]+=a1.w*b3.y; acc[6]+=a1.w*b3.z; acc[7]+=a1.w*b3.w;
        acc[8]+=a2.w*b3.x; acc[9]+=a2.w*b3.y; acc[10]+=a2.w*b3.z; acc[11]+=a2.w*b3.w;
        acc[12]+=a3.w*b3.x; acc[13]+=a3.w*b3.y; acc[14]+=a3.w*b3.z; acc[15]+=a3.w*b3.w;
    }
}

// ---------------- finalize + combine: both NS chains in one 512-thread block ----------------
// grid 8 (one block per label). half 0 = content (Wh=cov^-1/2), half 1 = style (Co=cov^1/2).
__global__ void __launch_bounds__(512) finalize_combine(const int* nlab_ptr) {
    const int l = blockIdx.x, tid = threadIdx.x;
    const int half = tid >> 8, ht = tid & 255;
    extern __shared__ float sm[];
    float* B0 = sm + half * (5*64*PITCH);
    float* Y  = B0;
    float* Z  = Y  + 64*PITCH;
    float* M  = Z  + 64*PITCH;
    float* Y2 = M  + 64*PITCH;
    float* Z2 = Y2 + 64*PITCH;
    __shared__ float sh_red[2][64];
    __shared__ float sh_c[2];
    __shared__ float sh_muc[64], sh_mus[64], sh_b[64];

    const float nc = g_cntc[l], ns = g_cnts[l];
    const float n  = half ? ns : nc;
    const bool buildI = (n < 10.5f);
    const float* S2 = half ? g_S2s : g_S2c;
    const float* S1 = half ? g_S1s : g_S1c;

    const float inv_n = 1.f / fmaxf(n, 1.f);
    const float nm1 = n - 1.f;
    const float invdiv = 1.f / ((nm1 == 0.f) ? 1e-5f : nm1);
    for (int e = ht; e < 4096; e += 256) {
        const int i = e >> 6, j = e & 63;
        float v;
        if (buildI) v = (i == j) ? 1.f : 0.f;
        else {
            float mui = S1[l*64 + i] * inv_n;
            float muj = S1[l*64 + j] * inv_n;
            v = (S2[l*4096 + e] - n*mui*muj) * invdiv;
            if (!half && i == j) v += 1.f;
        }
        Y[i*PITCH + j] = v;
        Z[i*PITCH + j] = (i == j) ? 1.f : 0.f;
    }
    if (ht < 64) {
        if (half == 0) sh_muc[ht] = g_S1c[l*64 + ht] / fmaxf(nc, 1.f);
        else           sh_mus[ht] = g_S1s[l*64 + ht] / fmaxf(ns, 1.f);
    }
    if (tid < 64) sh_b[tid] = 0.f;
    __syncthreads();
    if (ht < 64) {
        float rs = 0.f;
        for (int j = 0; j < 64; j++) rs += fabsf(Y[ht*PITCH + j]);
        sh_red[half][ht] = rs;
    }
    __syncthreads();
    if (ht == 0) {
        float m = 1e-30f;
        for (int i = 0; i < 64; i++) m = fmaxf(m, sh_red[half][i]);
        sh_c[half] = m;
    }
    __syncthreads();
    const float c = sh_c[half], invc = 1.f / c;
    for (int e = ht; e < 4096; e += 256)
        Y[(e >> 6)*PITCH + (e & 63)] *= invc;
    __syncthreads();

    const int ti = ht >> 4, tj = ht & 15;
    float *yA = Y, *zA = Z, *yB = Y2, *zB = Z2;
    for (int it = 0; it < NS_ITERS; it++) {
        float accM[16];
#pragma unroll
        for (int q = 0; q < 16; q++) accM[q] = 0.f;
        mm64v(zA, yA, accM, ti, tj);
#pragma unroll
        for (int a = 0; a < 4; a++) {
            float4 v = make_float4(accM[a*4+0], accM[a*4+1], accM[a*4+2], accM[a*4+3]);
            *(float4*)&M[(4*ti + a)*PITCH + 4*tj] = v;
        }
        __syncthreads();
        float accY[16], accZ[16];
#pragma unroll
        for (int q = 0; q < 16; q++) { accY[q] = 0.f; accZ[q] = 0.f; }
        mm64v(yA, M, accY, ti, tj);
        mm64v(M, zA, accZ, ti, tj);
#pragma unroll
        for (int a = 0; a < 4; a++)
#pragma unroll
            for (int b = 0; b < 4; b++) {
                int r = 4*ti + a, cc = 4*tj + b;
                yB[r*PITCH + cc] = 1.5f*yA[r*PITCH + cc] - 0.5f*accY[a*4+b];
                zB[r*PITCH + cc] = 1.5f*zA[r*PITCH + cc] - 0.5f*accZ[a*4+b];
            }
        __syncthreads();
        float* t;
        t = yA; yA = yB; yB = t;
        t = zA; zA = zB; zB = t;
    }
    // canonical result into this half's M buffer (free after loop)
    {
        const float scale = half ? sqrtf(c) : rsqrtf(c);
        const float* R = half ? yA : zA;
        for (int e = ht; e < 4096; e += 256) {
            const int i = e >> 6, j = e & 63;
            M[i*PITCH + j] = buildI ? ((i == j) ? 1.f : 0.f) : R[i*PITCH + j] * scale;
        }
    }
    __syncthreads();

    // combine: T = Co @ Wh, Tt store, b = mu_s - T mu_c. All 512 threads: 2 rows x 4 cols.
    const float* Wh = sm + 2*64*PITCH;                  // half0 M
    const float* Co = sm + 5*64*PITCH + 2*64*PITCH;     // half1 M
    int nlab = nlab_ptr ? *nlab_ptr : 8;
    const bool valid = (l < nlab) && (nc > 10.f) && (ns > 10.f) &&
                       (nc < 100.f*ns) && (ns < 100.f*nc);
    const int rr = tid >> 4, cj = tid & 15;
    float a8[8];
#pragma unroll
    for (int q = 0; q < 8; q++) a8[q] = 0.f;
#pragma unroll 4
    for (int k0 = 0; k0 < 64; k0 += 4) {
        const float4 a0 = *(const float4*)&Co[(2*rr+0)*PITCH + k0];
        const float4 a1 = *(const float4*)&Co[(2*rr+1)*PITCH + k0];
        const float4 b0 = *(const float4*)&Wh[(k0+0)*PITCH + 4*cj];
        const float4 b1 = *(const float4*)&Wh[(k0+1)*PITCH + 4*cj];
        const float4 b2 = *(const float4*)&Wh[(k0+2)*PITCH + 4*cj];
        const float4 b3 = *(const float4*)&Wh[(k0+3)*PITCH + 4*cj];
        a8[0]+=a0.x*b0.x+a0.y*b1.x+a0.z*b2.x+a0.w*b3.x;
        a8[1]+=a0.x*b0.y+a0.y*b1.y+a0.z*b2.y+a0.w*b3.y;
        a8[2]+=a0.x*b0.z+a0.y*b1.z+a0.z*b2.z+a0.w*b3.z;
        a8[3]+=a0.x*b0.w+a0.y*b1.w+a0.z*b2.w+a0.w*b3.w;
        a8[4]+=a1.x*b0.x+a1.y*b1.x+a1.z*b2.x+a1.w*b3.x;
        a8[5]+=a1.x*b0.y+a1.y*b1.y+a1.z*b2.y+a1.w*b3.y;
        a8[6]+=a1.x*b0.z+a1.y*b1.z+a1.z*b2.z+a1.w*b3.z;
        a8[7]+=a1.x*b0.w+a1.y*b1.w+a1.z*b2.w+a1.w*b3.w;
    }
    float bpart[2] = {0.f, 0.f};
#pragma unroll
    for (int a = 0; a < 2; a++)
#pragma unroll
        for (int b = 0; b < 4; b++) {
            const int i = 2*rr + a, j = 4*cj + b;
            const float av = a8[a*4+b];
            g_Tt[l*4096 + j*64 + i] = valid ? av : ((i == j) ? 1.f : 0.f);
            bpart[a] += av * sh_muc[j];
        }
    atomicAdd(&sh_b[2*rr+0], bpart[0]);
    atomicAdd(&sh_b[2*rr+1], bpart[1]);
    __syncthreads();
    if (tid < 64) g_bv[l*64 + tid] = valid ? (sh_mus[tid] - sh_b[tid]) : 0.f;
}

// ---------------- apply: 512-px tile, 512 threads (16 warps), warp-per-quad ----------------
__global__ void __launch_bounds__(512)
apply_kernel(const float* __restrict__ X,
             const int*   __restrict__ segp,
             float*       __restrict__ out)
{
    extern __shared__ float sm[];
    float* As = sm;                    // 64 * APA, column = sorted pixel position
    float* Ts = sm + 64*APA;           // 64 * 66, Ts[k][c] = T[c][k]
    float4* As4 = (float4*)As;         // row stride APA/4 = 136
    __shared__ float sh_bv[64];
    __shared__ int sh_spos[TPA];
    __shared__ int sh_s[8], sh_e[8], sh_hist[8], sh_off[8];

    const int tid  = threadIdx.x;
    const int lane = tid & 31;
    const int w    = tid >> 5;         // 0..15
    const int base = blockIdx.x * TPA;

    if (tid < 8) sh_hist[tid] = 0;
    __syncthreads();
    int lb = segp[base + tid];
    lb = lb < 0 ? 0 : (lb > 7 ? 7 : lb);
    atomicAdd(&sh_hist[lb], 1);
    __syncthreads();
    if (tid == 0) {
        int a = 0;
#pragma unroll
        for (int i = 0; i < 8; i++) {
            sh_s[i] = a; sh_off[i] = a;
            const int he = a + sh_hist[i];
            sh_e[i] = he;
            a = (he + 3) & ~3;               // next label starts on a quad boundary
        }
    }
    __syncthreads();
    sh_spos[tid] = atomicAdd(&sh_off[lb], 1);
    __syncthreads();
    // zero the <=3 padding columns after each segment (first 256 threads cover 64ch x 4cols)
#pragma unroll
    for (int l = 0; l < 8; l++) {
        const int zb = sh_e[l], ze = (zb + 3) & ~3;
        if (ze > zb && tid < 256) {
            const int c = tid >> 2, pp = zb + (tid & 3);
            if (pp < ze) As[c*APA + pp] = 0.f;
        }
    }
    // stage features into label-sorted columns (gmem coalesced)
    for (int e = tid; e < CCH*TPA; e += 512) {
        const int p = e & 511, c = e >> 9;
        As[c*APA + sh_spos[p]] = X[(size_t)c*NPIX + base + p];
    }
    __syncthreads();

    for (int l = 0; l < 8; l++) {
        const int s = sh_s[l], e = sh_e[l];
        const int qn = ((e - s) + 3) >> 2;
        if (qn == 0) continue;                 // uniform across block
        for (int idx = tid; idx < 4096; idx += 512)
            Ts[(idx >> 6)*66 + (idx & 63)] = g_Tt[(l << 12) + idx];
        if (tid < 64) sh_bv[tid] = g_bv[(l << 6) + tid];
        __syncthreads();

        const int qs = s >> 2;
        for (int qq = w; qq < qn; qq += 16) {
            const int q = qs + qq;
            const float2 b2 = *(const float2*)&sh_bv[2*lane];
            float a0[4], a1[4];
#pragma unroll
            for (int u = 0; u < 4; u++) { a0[u] = 0.f; a1[u] = 0.f; }
#pragma unroll 8
            for (int k = 0; k < 64; k++) {
                const float2 tv = *(const float2*)&Ts[k*66 + 2*lane];
                const float4 xv = As4[k*136 + q];
                a0[0] += tv.x*xv.x; a0[1] += tv.x*xv.y; a0[2] += tv.x*xv.z; a0[3] += tv.x*xv.w;
                a1[0] += tv.y*xv.x; a1[1] += tv.y*xv.y; a1[2] += tv.y*xv.z; a1[3] += tv.y*xv.w;
            }
            __syncwarp();   // all lanes done reading this quad's columns
            *(float4*)&As[(2*lane+0)*APA + 4*q] =
                make_float4(a0[0]+b2.x, a0[1]+b2.x, a0[2]+b2.x, a0[3]+b2.x);
            *(float4*)&As[(2*lane+1)*APA + 4*q] =
                make_float4(a1[0]+b2.y, a1[1]+b2.y, a1[2]+b2.y, a1[3]+b2.y);
        }
        __syncthreads();
    }

    // coalesced write-back in original pixel order
    for (int e = tid; e < CCH*TPA; e += 512) {
        const int p = e & 511, c = e >> 9;
        out[(size_t)c*NPIX + base + p] = As[c*APA + sh_spos[p]];
    }
}

// ---------------- launch ----------------
extern "C" void kernel_launch(void* const* d_in, const int* in_sizes, int n_in,
                              void* d_out, int out_size)
{
    const float* Xc   = (const float*)d_in[0];
    const float* Xs   = (const float*)d_in[1];
    const int*   segc = (const int*)d_in[2];
    const int*   segs = (const int*)d_in[3];
    const int*   nlab = (n_in >= 5) ? (const int*)d_in[4] : nullptr;
    float* out = (float*)d_out;

    const int smem_stats = TP*SP*4;                 // 69632
    const int smem_fc    = 2*5*64*PITCH*4;          // 174080
    const int smem_apply = (64*APA + 64*66)*4;      // 156160

    cudaFuncSetAttribute(stats_kernel,     cudaFuncAttributeMaxDynamicSharedMemorySize, smem_stats);
    cudaFuncSetAttribute(finalize_combine, cudaFuncAttributeMaxDynamicSharedMemorySize, smem_fc);
    cudaFuncSetAttribute(apply_kernel,     cudaFuncAttributeMaxDynamicSharedMemorySize, smem_apply);

    stats_kernel<<<dim3(GX, 2, 2), 256, smem_stats>>>(Xc, Xs, segc, segs);
    reduce_kernel<<<261, 256>>>();
    finalize_combine<<<8, 512, smem_fc>>>(nlab);
    apply_kernel<<<NPIX/TPA, 512, smem_apply>>>(Xc, segc, out);
}

// round 8
// speedup vs baseline: 1.0556x; 1.0556x over previous
#include <cuda_runtime.h>
#include <math.h>

#define CCH   64
#define NPIX  (512*512)
#define TP    256          // stats tile pixels
#define GX    148          // stats grid.x
#define NT    (NPIX/TP)    // 1024 tiles
#define SP    68           // stats sorted-tile pitch (floats)
#define PITCH 68           // 64x64 matrix smem pitch (floats)
#define TPA   512          // apply tile pixels
#define APA   544          // apply smem pitch (floats)
#define TSF   66           // apply T pitch
#define TS_SZ (64*TSF)
#define NS_ITERS 7

// ---------------- global scratch (static __device__, no allocations) ----------------
__device__ float g_gram[2*2*GX*4*4096];  // [side][gy][block][ll][64*64]
__device__ float g_s1p [2*2*GX*4*64];    // per-slab channel sums
__device__ float g_cntp[2*2*GX*4];       // per-slab counts
__device__ float g_S1c[8*64];
__device__ float g_S1s[8*64];
__device__ float g_cntc[8];
__device__ float g_cnts[8];
__device__ float g_S2c[8*4096];
__device__ float g_S2s[8*4096];
__device__ float g_Tt[8*4096];   // T transposed: g_Tt[l][k*64+c] = T[c][k]
__device__ float g_bv[8*64];     // b = mu_s - T mu_c (0 if invalid)

#define FMA16(ACC, AV, BV) do { \
    ACC[0]  += AV.x*BV.x; ACC[1]  += AV.x*BV.y; ACC[2]  += AV.x*BV.z; ACC[3]  += AV.x*BV.w; \
    ACC[4]  += AV.y*BV.x; ACC[5]  += AV.y*BV.y; ACC[6]  += AV.y*BV.z; ACC[7]  += AV.y*BV.w; \
    ACC[8]  += AV.z*BV.x; ACC[9]  += AV.z*BV.y; ACC[10] += AV.z*BV.z; ACC[11] += AV.z*BV.w; \
    ACC[12] += AV.w*BV.x; ACC[13] += AV.w*BV.y; ACC[14] += AV.w*BV.z; ACC[15] += AV.w*BV.w; \
} while (0)

// ---------------- stats: sorted-compact staging, contiguous Gram loop ----------------
// grid (GX, 2, 2): y = label-group (4 labels), z = side. 256 threads.
__global__ void __launch_bounds__(256, 2)
stats_kernel(const float* __restrict__ Xc, const float* __restrict__ Xs,
             const int* __restrict__ segc, const int* __restrict__ segs)
{
    extern __shared__ float As[];            // 256 * SP floats, label-sorted rows
    __shared__ int sh_hist[4], sh_off[4], sh_seg[5];

    const int tid  = threadIdx.x;
    const int gy   = blockIdx.y;
    const int side = blockIdx.z;
    const float* X    = side ? Xs : Xc;
    const int*   segp = side ? segs : segc;
    const int l0 = gy * 4;
    const int ti = tid >> 4, tj = tid & 15;
    float* Ap = As + 4*ti;
    float* Bp = As + 4*tj;

    float acc[4][16];
#pragma unroll
    for (int a = 0; a < 4; a++)
#pragma unroll
        for (int b = 0; b < 16; b++) acc[a][b] = 0.f;
    float s1[4] = {0.f,0.f,0.f,0.f};
    float cl[4] = {0.f,0.f,0.f,0.f};
    const int sc = tid & 63, sq = tid >> 6;

    for (int tile = blockIdx.x; tile < NT; tile += GX) {
        const int base = tile * TP;
        __syncthreads();                       // guard As reuse
        if (tid < 4) sh_hist[tid] = 0;
        __syncthreads();
        int lb = segp[base + tid];
        lb = lb < 0 ? 0 : (lb > 7 ? 7 : lb);
        const int lidx = lb - l0;
        const bool ing = (lidx >= 0) && (lidx < 4);
        if (ing) atomicAdd(&sh_hist[lidx], 1);
        __syncthreads();
        if (tid == 0) {
            int a = 0;
#pragma unroll
            for (int i = 0; i < 4; i++) { sh_seg[i] = a; sh_off[i] = a; a += sh_hist[i]; }
            sh_seg[4] = a;
        }
        __syncthreads();
        const int sp = ing ? atomicAdd(&sh_off[lidx], 1) : -1;
        // stage own pixel's 64 channels into sorted row sp; STS.128 packed
        if (sp >= 0) {
            float* dst = As + sp*SP;
            const float* src = X + base + tid;
#pragma unroll
            for (int c4 = 0; c4 < 16; c4++) {
                float4 v;
                v.x = src[(size_t)(4*c4+0)*NPIX];
                v.y = src[(size_t)(4*c4+1)*NPIX];
                v.z = src[(size_t)(4*c4+2)*NPIX];
                v.w = src[(size_t)(4*c4+3)*NPIX];
                *(float4*)&dst[4*c4] = v;
            }
        }
        __syncthreads();

#pragma unroll
        for (int ll = 0; ll < 4; ll++) {
            const int s = sh_seg[ll], e = sh_seg[ll+1];
            int k = s;
#define GB(LL, KK) { const float4 av = *(const float4*)&Ap[(KK)*SP]; \
                     const float4 bv = *(const float4*)&Bp[(KK)*SP]; \
                     FMA16(acc[LL], av, bv); }
            for (; k + 4 <= e; k += 4) { GB(ll, k) GB(ll, k+1) GB(ll, k+2) GB(ll, k+3) }
            for (; k < e; k++) GB(ll, k)
        }
        // per-label channel sums: lanes read consecutive channels, conflict-free
#pragma unroll
        for (int ll = 0; ll < 4; ll++) {
            for (int k = sh_seg[ll] + sq; k < sh_seg[ll+1]; k += 4)
                s1[ll] += As[k*SP + sc];
        }
        if (tid == 0) {
#pragma unroll
            for (int ll = 0; ll < 4; ll++) cl[ll] += (float)(sh_seg[ll+1] - sh_seg[ll]);
        }
    }

    // flush partial Grams / s1 / cnt (non-atomic, own slab)
    const size_t sb = (size_t)(side*2 + gy)*GX + blockIdx.x;
    float* gp = g_gram + sb*16384;
#pragma unroll
    for (int ll = 0; ll < 4; ll++)
#pragma unroll
        for (int a = 0; a < 4; a++) {
            float4 v = make_float4(acc[ll][a*4+0], acc[ll][a*4+1],
                                   acc[ll][a*4+2], acc[ll][a*4+3]);
            *(float4*)&gp[ll*4096 + (4*ti + a)*64 + 4*tj] = v;
        }
#pragma unroll
    for (int ll = 0; ll < 4; ll++) {
        __syncthreads();
        As[tid] = s1[ll];
        __syncthreads();
        if (tid < 64)
            g_s1p[sb*256 + ll*64 + tid] = As[tid] + As[tid+64] + As[tid+128] + As[tid+192];
    }
    if (tid == 0) {
#pragma unroll
        for (int ll = 0; ll < 4; ll++) g_cntp[sb*4 + ll] = cl[ll];
    }
}

// ---------------- reduce partial Grams + s1 + cnt ----------------
__global__ void reduce_kernel() {
    const int idx = blockIdx.x * blockDim.x + threadIdx.x;
    if (idx < 65536) {
        const int side = idx >> 15, r = idx & 32767;
        const int l = r >> 12, gy = l >> 2, ll = l & 3;
        const float* p = g_gram + ((size_t)(side*2 + gy)*GX)*16384 + ll*4096 + (r & 4095);
        float s = 0.f;
#pragma unroll 4
        for (int b = 0; b < GX; b++) s += p[(size_t)b*16384];
        (side ? g_S2s : g_S2c)[r] = s;
    } else if (idx < 66560) {
        const int j = idx - 65536;
        const int side = j >> 9, r = j & 511;
        const int l = r >> 6, gy = l >> 2, ll = l & 3;
        const float* p = g_s1p + ((size_t)(side*2 + gy)*GX)*256 + ll*64 + (r & 63);
        float s = 0.f;
        for (int b = 0; b < GX; b++) s += p[(size_t)b*256];
        (side ? g_S1s : g_S1c)[r] = s;
    } else if (idx < 66576) {
        const int j = idx - 66560;
        const int side = j >> 3, l = j & 7, gy = l >> 2, ll = l & 3;
        const float* p = g_cntp + ((size_t)(side*2 + gy)*GX)*4 + ll;
        float s = 0.f;
        for (int b = 0; b < GX; b++) s += p[(size_t)b*4];
        (side ? g_cnts : g_cntc)[l] = s;
    }
}

// ---------------- 64x64 matmul, 2-row accumulator tiles (512 threads per matrix) ----------------
__device__ __forceinline__ void mm64v2(const float* __restrict__ A,
                                       const float* __restrict__ B,
                                       float (&acc)[8], int ti, int tj)
{
#pragma unroll 4
    for (int k0 = 0; k0 < 64; k0 += 4) {
        const float4 a0 = *(const float4*)&A[(2*ti+0)*PITCH + k0];
        const float4 a1 = *(const float4*)&A[(2*ti+1)*PITCH + k0];
        const float4 b0 = *(const float4*)&B[(k0+0)*PITCH + 4*tj];
        const float4 b1 = *(const float4*)&B[(k0+1)*PITCH + 4*tj];
        const float4 b2 = *(const float4*)&B[(k0+2)*PITCH + 4*tj];
        const float4 b3 = *(const float4*)&B[(k0+3)*PITCH + 4*tj];
        acc[0]+=a0.x*b0.x; acc[1]+=a0.x*b0.y; acc[2]+=a0.x*b0.z; acc[3]+=a0.x*b0.w;
        acc[4]+=a1.x*b0.x; acc[5]+=a1.x*b0.y; acc[6]+=a1.x*b0.z; acc[7]+=a1.x*b0.w;
        acc[0]+=a0.y*b1.x; acc[1]+=a0.y*b1.y; acc[2]+=a0.y*b1.z; acc[3]+=a0.y*b1.w;
        acc[4]+=a1.y*b1.x; acc[5]+=a1.y*b1.y; acc[6]+=a1.y*b1.z; acc[7]+=a1.y*b1.w;
        acc[0]+=a0.z*b2.x; acc[1]+=a0.z*b2.y; acc[2]+=a0.z*b2.z; acc[3]+=a0.z*b2.w;
        acc[4]+=a1.z*b2.x; acc[5]+=a1.z*b2.y; acc[6]+=a1.z*b2.z; acc[7]+=a1.z*b2.w;
        acc[0]+=a0.w*b3.x; acc[1]+=a0.w*b3.y; acc[2]+=a0.w*b3.z; acc[3]+=a0.w*b3.w;
        acc[4]+=a1.w*b3.x; acc[5]+=a1.w*b3.y; acc[6]+=a1.w*b3.z; acc[7]+=a1.w*b3.w;
    }
}

// ---------------- finalize + combine: both NS chains, 512 threads each ----------------
// grid 8 (one block per label), 1024 threads. half 0 = content, half 1 = style.
__global__ void __launch_bounds__(1024) finalize_combine(const int* nlab_ptr) {
    const int l = blockIdx.x, tid = threadIdx.x;
    const int half = tid >> 9, ht = tid & 511;
    extern __shared__ float sm[];
    float* B0 = sm + half * (5*64*PITCH);
    float* Y  = B0;
    float* Z  = Y  + 64*PITCH;
    float* M  = Z  + 64*PITCH;
    float* Y2 = M  + 64*PITCH;
    float* Z2 = Y2 + 64*PITCH;
    __shared__ float sh_red[2][64];
    __shared__ float sh_c[2];
    __shared__ float sh_muc[64], sh_mus[64], sh_b[64];

    const float nc = g_cntc[l], ns = g_cnts[l];
    const float n  = half ? ns : nc;
    const bool buildI = (n < 10.5f);
    const float* S2 = half ? g_S2s : g_S2c;
    const float* S1 = half ? g_S1s : g_S1c;

    const float inv_n = 1.f / fmaxf(n, 1.f);
    const float nm1 = n - 1.f;
    const float invdiv = 1.f / ((nm1 == 0.f) ? 1e-5f : nm1);
    for (int e = ht; e < 4096; e += 512) {
        const int i = e >> 6, j = e & 63;
        float v;
        if (buildI) v = (i == j) ? 1.f : 0.f;
        else {
            float mui = S1[l*64 + i] * inv_n;
            float muj = S1[l*64 + j] * inv_n;
            v = (S2[l*4096 + e] - n*mui*muj) * invdiv;
            if (!half && i == j) v += 1.f;
        }
        Y[i*PITCH + j] = v;
        Z[i*PITCH + j] = (i == j) ? 1.f : 0.f;
    }
    if (ht < 64) {
        if (half == 0) sh_muc[ht] = g_S1c[l*64 + ht] / fmaxf(nc, 1.f);
        else           sh_mus[ht] = g_S1s[l*64 + ht] / fmaxf(ns, 1.f);
    }
    if (tid < 64) sh_b[tid] = 0.f;
    __syncthreads();
    if (ht < 64) {
        float rs = 0.f;
        for (int j = 0; j < 64; j++) rs += fabsf(Y[ht*PITCH + j]);
        sh_red[half][ht] = rs;
    }
    __syncthreads();
    if (ht == 0) {
        float m = 1e-30f;
        for (int i = 0; i < 64; i++) m = fmaxf(m, sh_red[half][i]);
        sh_c[half] = m;
    }
    __syncthreads();
    const float c = sh_c[half], invc = 1.f / c;
    for (int e = ht; e < 4096; e += 512)
        Y[(e >> 6)*PITCH + (e & 63)] *= invc;
    __syncthreads();

    const int ti = ht >> 4, tj = ht & 15;   // 2 rows x 4 cols per thread
    float *yA = Y, *zA = Z, *yB = Y2, *zB = Z2;
    for (int it = 0; it < NS_ITERS; it++) {
        float accM[8];
#pragma unroll
        for (int q = 0; q < 8; q++) accM[q] = 0.f;
        mm64v2(zA, yA, accM, ti, tj);
#pragma unroll
        for (int a = 0; a < 2; a++) {
            float4 v = make_float4(accM[a*4+0], accM[a*4+1], accM[a*4+2], accM[a*4+3]);
            *(float4*)&M[(2*ti + a)*PITCH + 4*tj] = v;
        }
        __syncthreads();
        float accY[8], accZ[8];
#pragma unroll
        for (int q = 0; q < 8; q++) { accY[q] = 0.f; accZ[q] = 0.f; }
        mm64v2(yA, M, accY, ti, tj);
        mm64v2(M, zA, accZ, ti, tj);
#pragma unroll
        for (int a = 0; a < 2; a++)
#pragma unroll
            for (int b = 0; b < 4; b++) {
                int r = 2*ti + a, cc = 4*tj + b;
                yB[r*PITCH + cc] = 1.5f*yA[r*PITCH + cc] - 0.5f*accY[a*4+b];
                zB[r*PITCH + cc] = 1.5f*zA[r*PITCH + cc] - 0.5f*accZ[a*4+b];
            }
        __syncthreads();
        float* t;
        t = yA; yA = yB; yB = t;
        t = zA; zA = zB; zB = t;
    }
    // canonical result into this half's M buffer
    {
        const float scale = half ? sqrtf(c) : rsqrtf(c);
        const float* R = half ? yA : zA;
        for (int e = ht; e < 4096; e += 512) {
            const int i = e >> 6, j = e & 63;
            M[i*PITCH + j] = buildI ? ((i == j) ? 1.f : 0.f) : R[i*PITCH + j] * scale;
        }
    }
    __syncthreads();

    // combine: T = Co @ Wh, Tt store, b = mu_s - T mu_c. 1024 threads: 1 row x 4 cols.
    const float* Wh = sm + 2*64*PITCH;                  // half0 M
    const float* Co = sm + 5*64*PITCH + 2*64*PITCH;     // half1 M
    int nlab = nlab_ptr ? *nlab_ptr : 8;
    const bool valid = (l < nlab) && (nc > 10.f) && (ns > 10.f) &&
                       (nc < 100.f*ns) && (ns < 100.f*nc);
    const int ri = tid >> 4, cj = tid & 15;
    float a4[4] = {0.f, 0.f, 0.f, 0.f};
#pragma unroll 4
    for (int k0 = 0; k0 < 64; k0 += 4) {
        const float4 a0 = *(const float4*)&Co[ri*PITCH + k0];
        const float4 b0 = *(const float4*)&Wh[(k0+0)*PITCH + 4*cj];
        const float4 b1 = *(const float4*)&Wh[(k0+1)*PITCH + 4*cj];
        const float4 b2 = *(const float4*)&Wh[(k0+2)*PITCH + 4*cj];
        const float4 b3 = *(const float4*)&Wh[(k0+3)*PITCH + 4*cj];
        a4[0]+=a0.x*b0.x+a0.y*b1.x+a0.z*b2.x+a0.w*b3.x;
        a4[1]+=a0.x*b0.y+a0.y*b1.y+a0.z*b2.y+a0.w*b3.y;
        a4[2]+=a0.x*b0.z+a0.y*b1.z+a0.z*b2.z+a0.w*b3.z;
        a4[3]+=a0.x*b0.w+a0.y*b1.w+a0.z*b2.w+a0.w*b3.w;
    }
    float bp = 0.f;
#pragma unroll
    for (int b = 0; b < 4; b++) {
        const int j = 4*cj + b;
        g_Tt[l*4096 + j*64 + ri] = valid ? a4[b] : ((ri == j) ? 1.f : 0.f);
        bp += a4[b] * sh_muc[j];
    }
    atomicAdd(&sh_b[ri], bp);
    __syncthreads();
    if (tid < 64) g_bv[l*64 + tid] = valid ? (sh_mus[tid] - sh_b[tid]) : 0.f;
}

// ---------------- apply: 512-px tile, 512 threads, 4 labels per phase ----------------
__global__ void __launch_bounds__(512)
apply_kernel(const float* __restrict__ X,
             const int*   __restrict__ segp,
             float*       __restrict__ out)
{
    extern __shared__ float sm[];
    float* As = sm;                    // 64 * APA
    float* Ts = sm + 64*APA;           // 4 * TS_SZ, Ts[ll][k][c]
    float4* As4 = (float4*)As;         // row stride APA/4 = 136
    __shared__ float sh_bv[4][64];
    __shared__ int sh_spos[TPA];
    __shared__ int sh_qlab[144];
    __shared__ int sh_sn[9];           // quad-padded segment starts; sn[8] = total
    __shared__ int sh_e[8], sh_hist[8], sh_off[8];

    const int tid  = threadIdx.x;
    const int lane = tid & 31;
    const int w    = tid >> 5;         // 0..15
    const int base = blockIdx.x * TPA;

    if (tid < 8) sh_hist[tid] = 0;
    __syncthreads();
    int lb = segp[base + tid];
    lb = lb < 0 ? 0 : (lb > 7 ? 7 : lb);
    atomicAdd(&sh_hist[lb], 1);
    __syncthreads();
    if (tid == 0) {
        int a = 0;
#pragma unroll
        for (int i = 0; i < 8; i++) {
            sh_sn[i] = a; sh_off[i] = a;
            sh_e[i] = a + sh_hist[i];
            a = (sh_e[i] + 3) & ~3;
        }
        sh_sn[8] = a;
    }
    __syncthreads();
    sh_spos[tid] = atomicAdd(&sh_off[lb], 1);
    // quad -> label map
    if (tid < 144) {
        int l = 0;
#pragma unroll
        for (int j = 1; j < 8; j++) if (4*tid >= sh_sn[j]) l = j;
        sh_qlab[tid] = l;
    }
    __syncthreads();
    // zero the <=3 padding columns after each segment
#pragma unroll
    for (int l = 0; l < 8; l++) {
        const int zb = sh_e[l], ze = (zb + 3) & ~3;
        if (ze > zb && tid < 256) {
            const int c = tid >> 2, pp = zb + (tid & 3);
            if (pp < ze) As[c*APA + pp] = 0.f;
        }
    }
    // stage features into label-sorted columns (gmem coalesced)
    for (int e = tid; e < CCH*TPA; e += 512) {
        const int p = e & 511, c = e >> 9;
        As[c*APA + sh_spos[p]] = X[(size_t)c*NPIX + base + p];
    }
    __syncthreads();

#pragma unroll
    for (int ph = 0; ph < 2; ph++) {
        const int lbase = 4*ph;
        // load this phase's 4 T matrices + biases
        for (int idx = tid; idx < 4*4096; idx += 512) {
            const int ll = idx >> 12, e = idx & 4095;
            Ts[ll*TS_SZ + (e >> 6)*TSF + (e & 63)] = g_Tt[((lbase + ll) << 12) + e];
        }
        if (tid < 256) sh_bv[tid >> 6][tid & 63] = g_bv[((lbase + (tid >> 6)) << 6) + (tid & 63)];
        __syncthreads();

        const int qlo = sh_sn[lbase] >> 2;
        const int qhi = sh_sn[lbase + 4] >> 2;
        for (int q = qlo + w; q < qhi; q += 16) {
            const int l4 = sh_qlab[q] - lbase;
            const float* Tp = Ts + l4*TS_SZ + 2*lane;
            const float2 b2 = *(const float2*)&sh_bv[l4][2*lane];
            float a0[4], a1[4];
#pragma unroll
            for (int u = 0; u < 4; u++) { a0[u] = 0.f; a1[u] = 0.f; }
#pragma unroll 8
            for (int k = 0; k < 64; k++) {
                const float2 tv = *(const float2*)&Tp[k*TSF];
                const float4 xv = As4[k*136 + q];
                a0[0] += tv.x*xv.x; a0[1] += tv.x*xv.y; a0[2] += tv.x*xv.z; a0[3] += tv.x*xv.w;
                a1[0] += tv.y*xv.x; a1[1] += tv.y*xv.y; a1[2] += tv.y*xv.z; a1[3] += tv.y*xv.w;
            }
            __syncwarp();   // all lanes done reading this quad's columns
            *(float4*)&As[(2*lane+0)*APA + 4*q] =
                make_float4(a0[0]+b2.x, a0[1]+b2.x, a0[2]+b2.x, a0[3]+b2.x);
            *(float4*)&As[(2*lane+1)*APA + 4*q] =
                make_float4(a1[0]+b2.y, a1[1]+b2.y, a1[2]+b2.y, a1[3]+b2.y);
        }
        __syncthreads();
    }

    // coalesced write-back in original pixel order
    for (int e = tid; e < CCH*TPA; e += 512) {
        const int p = e & 511, c = e >> 9;
        out[(size_t)c*NPIX + base + p] = As[c*APA + sh_spos[p]];
    }
}

// ---------------- launch ----------------
extern "C" void kernel_launch(void* const* d_in, const int* in_sizes, int n_in,
                              void* d_out, int out_size)
{
    const float* Xc   = (const float*)d_in[0];
    const float* Xs   = (const float*)d_in[1];
    const int*   segc = (const int*)d_in[2];
    const int*   segs = (const int*)d_in[3];
    const int*   nlab = (n_in >= 5) ? (const int*)d_in[4] : nullptr;
    float* out = (float*)d_out;

    const int smem_stats = TP*SP*4;                 // 69632
    const int smem_fc    = 2*5*64*PITCH*4;          // 174080
    const int smem_apply = (64*APA + 4*TS_SZ)*4;    // 206848

    cudaFuncSetAttribute(stats_kernel,     cudaFuncAttributeMaxDynamicSharedMemorySize, smem_stats);
    cudaFuncSetAttribute(finalize_combine, cudaFuncAttributeMaxDynamicSharedMemorySize, smem_fc);
    cudaFuncSetAttribute(apply_kernel,     cudaFuncAttributeMaxDynamicSharedMemorySize, smem_apply);

    stats_kernel<<<dim3(GX, 2, 2), 256, smem_stats>>>(Xc, Xs, segc, segs);
    reduce_kernel<<<261, 256>>>();
    finalize_combine<<<8, 1024, smem_fc>>>(nlab);
    apply_kernel<<<NPIX/TPA, 512, smem_apply>>>(Xc, segc, out);
}